// round 6
// baseline (speedup 1.0000x reference)
#include <cuda_runtime.h>
#include <math.h>

#define SEQ  1024
#define NF   256
#define H    1024
#define G4   4096
#define OUTN 1024
#define NB   128   // persistent CTAs (1/SM; all co-resident)
#define JPB  8     // h indices per CTA

typedef unsigned long long u64;

// ---------------- device scratch ----------------
__device__ float    g_gx[(size_t)SEQ * G4];        // x@W_ih^T + b_ih + b_hh (16 MB)
__device__ float    g_h[(size_t)(SEQ + 1) * H];
__device__ float    g_logits[(size_t)SEQ * OUTN];
__device__ float    g_lse[SEQ];
__device__ u64      g_sorted[(size_t)SEQ * OUTN];  // per-row descending (key<<32|1023-idx)
__device__ unsigned g_flag[(size_t)(SEQ + 1) * NB]; // per-CTA per-step flags

__device__ __forceinline__ float sigm(float x) { return 1.0f / (1.0f + __expf(-x)); }

__device__ __forceinline__ unsigned ld_acq(const unsigned* p) {
    unsigned v;
    asm volatile("ld.acquire.gpu.global.u32 %0, [%1];" : "=r"(v) : "l"(p) : "memory");
    return v;
}
__device__ __forceinline__ void st_rel(unsigned* p, unsigned v) {
    asm volatile("st.release.gpu.global.u32 [%0], %1;" :: "l"(p), "r"(v) : "memory");
}

// ---------------- Kernel A: gx[t][r] = b_ih[r]+b_hh[r] + X[t]·W_ih[r] ----------------
__global__ void precompute_gx(const float* __restrict__ X,
                              const float* __restrict__ Wih,
                              const float* __restrict__ bih,
                              const float* __restrict__ bhh) {
    __shared__ float Xs[32 * NF];
    const int r  = blockIdx.x * 256 + threadIdx.x;
    const int t0 = blockIdx.y * 32;

    for (int i = threadIdx.x; i < 32 * NF; i += 256)
        Xs[i] = X[(size_t)t0 * NF + i];
    __syncthreads();

    const float bias = bih[r] + bhh[r];
    float acc[32];
#pragma unroll
    for (int tt = 0; tt < 32; tt++) acc[tt] = bias;

    const float4* Wr = (const float4*)(Wih + (size_t)r * NF);
    for (int k4 = 0; k4 < NF / 4; k4++) {
        float4 wv = Wr[k4];
#pragma unroll
        for (int tt = 0; tt < 32; tt++) {
            float4 xv = *(const float4*)&Xs[tt * NF + k4 * 4];
            acc[tt] += wv.x * xv.x + wv.y * xv.y + wv.z * xv.z + wv.w * xv.w;
        }
    }
#pragma unroll
    for (int tt = 0; tt < 32; tt++)
        g_gx[(size_t)(t0 + tt) * G4 + r] = acc[tt];
}

// ---------------- Kernel B: persistent LSTM, W_hh in REGISTERS ----------------
// CTA b owns j = b*8..b*8+7; warp w handles j = b*8+w.
// Lane l permanently holds Whh[4 gates][j][cols (cc*32+l)*4..+3] = 32 float4 in regs.
__global__ void __launch_bounds__(256, 1)
lstm_recurrence(const float* __restrict__ enc,
                const float* __restrict__ Whh,
                const float* __restrict__ Wout,
                const float* __restrict__ bout) {
    __shared__ float  hs[H];            // 4 KB
    __shared__ float4 wout_s[8 * 256];  // 32 KB

    const int b = blockIdx.x, tid = threadIdx.x;
    const int w = tid >> 5, l = tid & 31;
    const int j = b * JPB + w;

    // ---- Whh into registers (coalesced: lane-stride float4) ----
    float4 wh[32];   // [g*8+cc]
    const float4* Whh4 = (const float4*)Whh;
#pragma unroll
    for (int g = 0; g < 4; g++)
#pragma unroll
        for (int cc = 0; cc < 8; cc++)
            wh[g * 8 + cc] = Whh4[(size_t)(g * H + j) * 256 + cc * 32 + l];

    // ---- Wout rows into smem ----
    const float4* Wout4 = (const float4*)Wout;
    for (int ww = 0; ww < 8; ww++)
        wout_s[ww * 256 + tid] = Wout4[(size_t)(b * JPB + ww) * 256 + tid];

    const float c0j   = enc[(size_t)(SEQ - 1) * H + j];
    const float boutj = bout[j];

    float gxv_next = (l < 4) ? g_gx[(size_t)0 * G4 + l * H + j] : 0.0f;
    __syncthreads();

    float4 hr[8];

    for (int t = 0; t < SEQ; t++) {
        // ---- wait: each of 128 threads polls one CTA's flag (parallel, no atomics) ----
        if (t > 0) {
            if (tid < NB) { while (ld_acq(&g_flag[(size_t)t * NB + tid]) == 0) {} }
            __syncthreads();
        }

        // ---- stage h_t ----
        ((float4*)hs)[tid] = ((const float4*)(g_h + (size_t)t * H))[tid];
        float gxv = gxv_next;
        __syncthreads();

        if (t + 1 < SEQ && l < 4) gxv_next = g_gx[(size_t)(t + 1) * G4 + l * H + j];

        // ---- gates from register weights ----
        float a0 = 0.f, a1 = 0.f, a2 = 0.f, a3 = 0.f;
#pragma unroll
        for (int cc = 0; cc < 8; cc++) {
            float4 hv = ((float4*)hs)[cc * 32 + l];
            hr[cc] = hv;
            float4 w0 = wh[0 * 8 + cc], w1 = wh[1 * 8 + cc];
            float4 w2 = wh[2 * 8 + cc], w3 = wh[3 * 8 + cc];
            a0 += w0.x * hv.x + w0.y * hv.y + w0.z * hv.z + w0.w * hv.w;
            a1 += w1.x * hv.x + w1.y * hv.y + w1.z * hv.z + w1.w * hv.w;
            a2 += w2.x * hv.x + w2.y * hv.y + w2.z * hv.z + w2.w * hv.w;
            a3 += w3.x * hv.x + w3.y * hv.y + w3.z * hv.z + w3.w * hv.w;
        }
#pragma unroll
        for (int off = 16; off; off >>= 1) {
            a0 += __shfl_down_sync(0xffffffffu, a0, off);
            a1 += __shfl_down_sync(0xffffffffu, a1, off);
            a2 += __shfl_down_sync(0xffffffffu, a2, off);
            a3 += __shfl_down_sync(0xffffffffu, a3, off);
        }
        float gx0 = __shfl_sync(0xffffffffu, gxv, 0);
        float gx1 = __shfl_sync(0xffffffffu, gxv, 1);
        float gx2 = __shfl_sync(0xffffffffu, gxv, 2);
        float gx3 = __shfl_sync(0xffffffffu, gxv, 3);
        if (l == 0) {
            float ig = sigm(a0 + gx0);
            float fg = sigm(a1 + gx1);
            float gg = tanhf(a2 + gx2);
            float og = sigm(a3 + gx3);
            float c  = fg * c0j + ig * gg;
            g_h[(size_t)(t + 1) * H + j] = og * tanhf(c);
        }
        __syncthreads();

        // ---- publish: one release store per CTA ----
        if (tid == 0) st_rel(&g_flag[(size_t)(t + 1) * NB + b], 1u);

        // ---- hidden in barrier slack: logits[t-1] = h_t · Wout_j ----
        if (t > 0) {
            float s = 0.f;
#pragma unroll
            for (int cc = 0; cc < 8; cc++) {
                float4 wv = wout_s[w * 256 + cc * 32 + l];
                float4 hv = hr[cc];
                s += wv.x * hv.x + wv.y * hv.y + wv.z * hv.z + wv.w * hv.w;
            }
#pragma unroll
            for (int off = 16; off; off >>= 1) s += __shfl_down_sync(0xffffffffu, s, off);
            if (l == 0) g_logits[(size_t)(t - 1) * OUTN + j] = s + boutj;
        }
    }

    // ---- epilogue: logits[SEQ-1] from h_SEQ ----
    if (tid < NB) { while (ld_acq(&g_flag[(size_t)SEQ * NB + tid]) == 0) {} }
    __syncthreads();
    ((float4*)hs)[tid] = ((const float4*)(g_h + (size_t)SEQ * H))[tid];
    __syncthreads();
    {
        float s = 0.f;
#pragma unroll
        for (int cc = 0; cc < 8; cc++) {
            float4 hv = ((float4*)hs)[cc * 32 + l];
            float4 wv = wout_s[w * 256 + cc * 32 + l];
            s += wv.x * hv.x + wv.y * hv.y + wv.z * hv.z + wv.w * hv.w;
        }
#pragma unroll
        for (int off = 16; off; off >>= 1) s += __shfl_down_sync(0xffffffffu, s, off);
        if (l == 0) g_logits[(size_t)(SEQ - 1) * OUTN + j] = s + boutj;
    }
}

// ---------------- Kernel C: per-row logsumexp ----------------
__global__ void row_lse() {
    const int t = blockIdx.x, tid = threadIdx.x, w = tid >> 5, l = tid & 31;
    __shared__ float red[8];
    float v[4];
#pragma unroll
    for (int k = 0; k < 4; k++) v[k] = g_logits[(size_t)t * OUTN + tid + k * 256];
    float m = fmaxf(fmaxf(v[0], v[1]), fmaxf(v[2], v[3]));
#pragma unroll
    for (int off = 16; off; off >>= 1) m = fmaxf(m, __shfl_xor_sync(0xffffffffu, m, off));
    if (l == 0) red[w] = m;
    __syncthreads();
    float M = red[0];
#pragma unroll
    for (int i = 1; i < 8; i++) M = fmaxf(M, red[i]);
    float s = 0.f;
#pragma unroll
    for (int k = 0; k < 4; k++) s += expf(v[k] - M);
#pragma unroll
    for (int off = 16; off; off >>= 1) s += __shfl_xor_sync(0xffffffffu, s, off);
    __syncthreads();
    if (l == 0) red[w] = s;
    __syncthreads();
    if (tid == 0) {
        float S = 0.f;
#pragma unroll
        for (int i = 0; i < 8; i++) S += red[i];
        g_lse[t] = M + logf(S);
    }
}

// ---------------- Kernel S: bitonic sort each logits row (descending u64 keys) ----------------
// key = (monotone(float) << 32) | (1023 - idx)  -> max key = (max value, min index)
__global__ void sort_rows() {
    __shared__ u64 key[OUTN];
    const int t = blockIdx.x, tid = threadIdx.x;

    for (int i = tid; i < OUTN; i += 256) {
        unsigned u = __float_as_uint(g_logits[(size_t)t * OUTN + i]);
        unsigned m = (u & 0x80000000u) ? ~u : (u | 0x80000000u);
        key[i] = ((u64)m << 32) | (u64)(OUTN - 1 - i);
    }
    __syncthreads();

    for (int k = 2; k <= OUTN; k <<= 1) {
        for (int jj = k >> 1; jj > 0; jj >>= 1) {
            for (int i = tid; i < OUTN; i += 256) {
                int ix = i ^ jj;
                if (ix > i) {
                    bool descend = (i & k) == 0;
                    u64 a = key[i], c = key[ix];
                    bool sw = descend ? (a < c) : (a > c);
                    if (sw) { key[i] = c; key[ix] = a; }
                }
            }
            __syncthreads();
        }
    }

    for (int i = tid; i < OUTN; i += 256)
        g_sorted[(size_t)t * OUTN + i] = key[i];
}

// ---------------- Kernel D: ballot-based tour selection over sorted candidates ----------------
__global__ void tour_select(float* __restrict__ out, int out_size) {
    __shared__ unsigned vis[32];
    const int l = threadIdx.x;
    vis[l] = 0;
    __syncwarp();

    u64 cur = g_sorted[l];       // rank-l candidate of row 0
    float lse_c = g_lse[0];

    for (int t = 0; t < SEQ; t++) {
        u64 nxt = 0; float lse_n = 0.f;
        if (t + 1 < SEQ) {
            nxt   = g_sorted[(size_t)(t + 1) * OUTN + l];
            lse_n = g_lse[t + 1];
        }

        u64 key = cur;
        int batch = 0;
        unsigned ballot;
        for (;;) {
            unsigned idx  = OUTN - 1 - (unsigned)(key & 0xFFFFFFFFu);
            bool unvis = ((vis[idx >> 5] >> (idx & 31)) & 1u) == 0u;
            ballot = __ballot_sync(0xffffffffu, unvis);
            if (ballot) break;
            batch++;                               // rare: top-32*batch all visited
            key = g_sorted[(size_t)t * OUTN + batch * 32 + l];
        }
        int wl = __ffs(ballot) - 1;                // lowest lane = best rank
        u64 wkey = __shfl_sync(0xffffffffu, key, wl);
        unsigned widx = OUTN - 1 - (unsigned)(wkey & 0xFFFFFFFFu);
        if (l == 0) {
            unsigned m = (unsigned)(wkey >> 32);
            unsigned u = (m & 0x80000000u) ? (m ^ 0x80000000u) : ~m;
            float val = __uint_as_float(u);
            if (t < out_size)       out[t] = (float)widx;
            if (SEQ + t < out_size) out[SEQ + t] = val - lse_c;
            vis[widx >> 5] |= 1u << (widx & 31);
        }
        __syncwarp();

        cur = nxt; lse_c = lse_n;
    }
}

// ---------------- launch ----------------
extern "C" void kernel_launch(void* const* d_in, const int* in_sizes, int n_in,
                              void* d_out, int out_size) {
    const float* X    = (const float*)d_in[0];
    const float* enc  = (const float*)d_in[1];
    const float* Wih  = (const float*)d_in[2];
    const float* Whh  = (const float*)d_in[3];
    const float* bih  = (const float*)d_in[4];
    const float* bhh  = (const float*)d_in[5];
    const float* Wout = (const float*)d_in[6];
    const float* bout = (const float*)d_in[7];
    float* out = (float*)d_out;

    // per-launch resets (graph-capturable async memsets)
    void* flagAddr = nullptr; cudaGetSymbolAddress(&flagAddr, g_flag);
    cudaMemsetAsync(flagAddr, 0, (size_t)(SEQ + 1) * NB * sizeof(unsigned));
    void* hAddr = nullptr; cudaGetSymbolAddress(&hAddr, g_h);
    cudaMemsetAsync(hAddr, 0, H * sizeof(float));   // h_0 = 0

    precompute_gx<<<dim3(16, 32), 256>>>(X, Wih, bih, bhh);
    lstm_recurrence<<<NB, 256>>>(enc, Whh, Wout, bout);
    row_lse<<<SEQ, 256>>>();
    sort_rows<<<SEQ, 256>>>();
    tour_select<<<1, 32>>>(out, out_size);
}

// round 8
// speedup vs baseline: 1.2320x; 1.2320x over previous
#include <cuda_runtime.h>
#include <math.h>

#define SEQ  1024
#define NF   256
#define H    1024
#define G4   4096
#define OUTN 1024
#define NB   128   // persistent CTAs (1/SM; all co-resident)
#define JPB  8     // h indices per CTA

typedef unsigned long long u64;

// ---------------- device scratch ----------------
__device__ float    g_gx[(size_t)SEQ * G4];        // x@W_ih^T + b_ih + b_hh (16 MB)
__device__ float    g_h[(size_t)(SEQ + 1) * H];
__device__ float    g_logits[(size_t)SEQ * OUTN];
__device__ float    g_lse[SEQ];
__device__ u64      g_sorted[(size_t)SEQ * OUTN];  // per-row descending (key<<32 | 1023-idx)
__device__ unsigned g_done[SEQ + 1];               // per-step arrival counters (memset/launch)

__device__ __forceinline__ float sigm(float x) { return 1.0f / (1.0f + __expf(-x)); }

__device__ __forceinline__ unsigned ld_acq(const unsigned* p) {
    unsigned v;
    asm volatile("ld.acquire.gpu.global.u32 %0, [%1];" : "=r"(v) : "l"(p) : "memory");
    return v;
}
__device__ __forceinline__ void red_rel(unsigned* p) {
    asm volatile("red.release.gpu.global.add.u32 [%0], 1;" :: "l"(p) : "memory");
}

// ---------------- Kernel A: gx[t][r] = b_ih[r]+b_hh[r] + X[t]·W_ih[r] ----------------
__global__ void precompute_gx(const float* __restrict__ X,
                              const float* __restrict__ Wih,
                              const float* __restrict__ bih,
                              const float* __restrict__ bhh) {
    __shared__ float Xs[32 * NF];
    const int r  = blockIdx.x * 256 + threadIdx.x;
    const int t0 = blockIdx.y * 32;

    for (int i = threadIdx.x; i < 32 * NF; i += 256)
        Xs[i] = X[(size_t)t0 * NF + i];
    __syncthreads();

    const float bias = bih[r] + bhh[r];
    float acc[32];
#pragma unroll
    for (int tt = 0; tt < 32; tt++) acc[tt] = bias;

    const float4* Wr = (const float4*)(Wih + (size_t)r * NF);
    for (int k4 = 0; k4 < NF / 4; k4++) {
        float4 wv = Wr[k4];
#pragma unroll
        for (int tt = 0; tt < 32; tt++) {
            float4 xv = *(const float4*)&Xs[tt * NF + k4 * 4];
            acc[tt] += wv.x * xv.x + wv.y * xv.y + wv.z * xv.z + wv.w * xv.w;
        }
    }
#pragma unroll
    for (int tt = 0; tt < 32; tt++)
        g_gx[(size_t)(t0 + tt) * G4 + r] = acc[tt];
}

// ---------------- Kernel B: persistent LSTM — Whh in registers, R5 counter barrier ----
// CTA b owns j = b*8..b*8+7; warp w handles j = b*8+w.
// Lane l permanently holds Whh[4 gates][j][cols (cc*32+l)*4..+3] = 32 float4 in regs.
__global__ void __launch_bounds__(256, 1)
lstm_recurrence(const float* __restrict__ enc,
                const float* __restrict__ Whh,
                const float* __restrict__ Wout,
                const float* __restrict__ bout) {
    __shared__ float  hs[H];            // 4 KB
    __shared__ float4 wout_s[8 * 256];  // 32 KB

    const int b = blockIdx.x, tid = threadIdx.x;
    const int w = tid >> 5, l = tid & 31;
    const int j = b * JPB + w;

    // ---- Whh into registers (coalesced lane-stride float4) ----
    float4 wh[32];   // [g*8+cc]
    const float4* Whh4 = (const float4*)Whh;
#pragma unroll
    for (int g = 0; g < 4; g++)
#pragma unroll
        for (int cc = 0; cc < 8; cc++)
            wh[g * 8 + cc] = Whh4[(size_t)(g * H + j) * 256 + cc * 32 + l];

    // ---- Wout rows into smem ----
    const float4* Wout4 = (const float4*)Wout;
    for (int ww = 0; ww < 8; ww++)
        wout_s[ww * 256 + tid] = Wout4[(size_t)(b * JPB + ww) * 256 + tid];

    const float c0j   = enc[(size_t)(SEQ - 1) * H + j];
    const float boutj = bout[j];

    float gxv_next = (l < 4) ? g_gx[(size_t)0 * G4 + l * H + j] : 0.0f;
    __syncthreads();

    float4 hr[8];

    for (int t = 0; t < SEQ; t++) {
        // ---- wait for h_t: single poller on one counter (R5-proven) ----
        if (t > 0) {
            if (tid == 0) { while (ld_acq(&g_done[t]) < NB) {} }
            __syncthreads();
        }

        // ---- stage h_t ----
        ((float4*)hs)[tid] = ((const float4*)(g_h + (size_t)t * H))[tid];
        float gxv = gxv_next;
        __syncthreads();

        if (t + 1 < SEQ && l < 4) gxv_next = g_gx[(size_t)(t + 1) * G4 + l * H + j];

        // ---- gates from register weights ----
        float a0 = 0.f, a1 = 0.f, a2 = 0.f, a3 = 0.f;
#pragma unroll
        for (int cc = 0; cc < 8; cc++) {
            float4 hv = ((float4*)hs)[cc * 32 + l];
            hr[cc] = hv;
            float4 w0 = wh[0 * 8 + cc], w1 = wh[1 * 8 + cc];
            float4 w2 = wh[2 * 8 + cc], w3 = wh[3 * 8 + cc];
            a0 += w0.x * hv.x + w0.y * hv.y + w0.z * hv.z + w0.w * hv.w;
            a1 += w1.x * hv.x + w1.y * hv.y + w1.z * hv.z + w1.w * hv.w;
            a2 += w2.x * hv.x + w2.y * hv.y + w2.z * hv.z + w2.w * hv.w;
            a3 += w3.x * hv.x + w3.y * hv.y + w3.z * hv.z + w3.w * hv.w;
        }
#pragma unroll
        for (int off = 16; off; off >>= 1) {
            a0 += __shfl_down_sync(0xffffffffu, a0, off);
            a1 += __shfl_down_sync(0xffffffffu, a1, off);
            a2 += __shfl_down_sync(0xffffffffu, a2, off);
            a3 += __shfl_down_sync(0xffffffffu, a3, off);
        }
        float gx0 = __shfl_sync(0xffffffffu, gxv, 0);
        float gx1 = __shfl_sync(0xffffffffu, gxv, 1);
        float gx2 = __shfl_sync(0xffffffffu, gxv, 2);
        float gx3 = __shfl_sync(0xffffffffu, gxv, 3);
        if (l == 0) {
            float ig = sigm(a0 + gx0);
            float fg = sigm(a1 + gx1);
            float gg = tanhf(a2 + gx2);
            float og = sigm(a3 + gx3);
            float c  = fg * c0j + ig * gg;
            g_h[(size_t)(t + 1) * H + j] = og * tanhf(c);
        }
        __syncthreads();

        // ---- arrive: one release-red per CTA ----
        if (tid == 0) red_rel(&g_done[t + 1]);

        // ---- hidden in barrier slack: logits[t-1] = h_t · Wout_j ----
        if (t > 0) {
            float s = 0.f;
#pragma unroll
            for (int cc = 0; cc < 8; cc++) {
                float4 wv = wout_s[w * 256 + cc * 32 + l];
                float4 hv = hr[cc];
                s += wv.x * hv.x + wv.y * hv.y + wv.z * hv.z + wv.w * hv.w;
            }
#pragma unroll
            for (int off = 16; off; off >>= 1) s += __shfl_down_sync(0xffffffffu, s, off);
            if (l == 0) g_logits[(size_t)(t - 1) * OUTN + j] = s + boutj;
        }
    }

    // ---- epilogue: logits[SEQ-1] from h_SEQ ----
    if (tid == 0) { while (ld_acq(&g_done[SEQ]) < NB) {} }
    __syncthreads();
    ((float4*)hs)[tid] = ((const float4*)(g_h + (size_t)SEQ * H))[tid];
    __syncthreads();
    {
        float s = 0.f;
#pragma unroll
        for (int cc = 0; cc < 8; cc++) {
            float4 hv = ((float4*)hs)[cc * 32 + l];
            float4 wv = wout_s[w * 256 + cc * 32 + l];
            s += wv.x * hv.x + wv.y * hv.y + wv.z * hv.z + wv.w * hv.w;
        }
#pragma unroll
        for (int off = 16; off; off >>= 1) s += __shfl_down_sync(0xffffffffu, s, off);
        if (l == 0) g_logits[(size_t)(SEQ - 1) * OUTN + j] = s + boutj;
    }
}

// ---------------- Kernel C: per-row logsumexp ----------------
__global__ void row_lse() {
    const int t = blockIdx.x, tid = threadIdx.x, w = tid >> 5, l = tid & 31;
    __shared__ float red[8];
    float v[4];
#pragma unroll
    for (int k = 0; k < 4; k++) v[k] = g_logits[(size_t)t * OUTN + tid + k * 256];
    float m = fmaxf(fmaxf(v[0], v[1]), fmaxf(v[2], v[3]));
#pragma unroll
    for (int off = 16; off; off >>= 1) m = fmaxf(m, __shfl_xor_sync(0xffffffffu, m, off));
    if (l == 0) red[w] = m;
    __syncthreads();
    float M = red[0];
#pragma unroll
    for (int i = 1; i < 8; i++) M = fmaxf(M, red[i]);
    float s = 0.f;
#pragma unroll
    for (int k = 0; k < 4; k++) s += expf(v[k] - M);
#pragma unroll
    for (int off = 16; off; off >>= 1) s += __shfl_xor_sync(0xffffffffu, s, off);
    __syncthreads();
    if (l == 0) red[w] = s;
    __syncthreads();
    if (tid == 0) {
        float S = 0.f;
#pragma unroll
        for (int i = 0; i < 8; i++) S += red[i];
        g_lse[t] = M + logf(S);
    }
}

// ---------------- Kernel S: bitonic sort each logits row (descending u64 keys) ----------------
// key = (monotone(float) << 32) | (1023 - idx)  -> max key = (max value, min index)
__global__ void sort_rows() {
    __shared__ u64 key[OUTN];
    const int t = blockIdx.x, tid = threadIdx.x;

    for (int i = tid; i < OUTN; i += 256) {
        unsigned u = __float_as_uint(g_logits[(size_t)t * OUTN + i]);
        unsigned m = (u & 0x80000000u) ? ~u : (u | 0x80000000u);
        key[i] = ((u64)m << 32) | (u64)(OUTN - 1 - i);
    }
    __syncthreads();

    for (int k = 2; k <= OUTN; k <<= 1) {
        for (int jj = k >> 1; jj > 0; jj >>= 1) {
            for (int i = tid; i < OUTN; i += 256) {
                int ix = i ^ jj;
                if (ix > i) {
                    bool descend = (i & k) == 0;
                    u64 a = key[i], c = key[ix];
                    bool sw = descend ? (a < c) : (a > c);
                    if (sw) { key[i] = c; key[ix] = a; }
                }
            }
            __syncthreads();
        }
    }

    for (int i = tid; i < OUTN; i += 256)
        g_sorted[(size_t)t * OUTN + i] = key[i];
}

// ---------------- Kernel D: ballot-based tour selection over sorted candidates ----------------
__global__ void tour_select(float* __restrict__ out, int out_size) {
    __shared__ unsigned vis[32];
    const int l = threadIdx.x;
    vis[l] = 0;
    __syncwarp();

    u64 cur = g_sorted[l];       // rank-l candidate of row 0
    float lse_c = g_lse[0];

    for (int t = 0; t < SEQ; t++) {
        u64 nxt = 0; float lse_n = 0.f;
        if (t + 1 < SEQ) {
            nxt   = g_sorted[(size_t)(t + 1) * OUTN + l];
            lse_n = g_lse[t + 1];
        }

        u64 key = cur;
        int batch = 0;
        unsigned ballot;
        for (;;) {
            unsigned idx  = OUTN - 1 - (unsigned)(key & 0xFFFFFFFFu);
            bool unvis = ((vis[idx >> 5] >> (idx & 31)) & 1u) == 0u;
            ballot = __ballot_sync(0xffffffffu, unvis);
            if (ballot) break;
            batch++;                               // rare: top-32*batch all visited
            key = g_sorted[(size_t)t * OUTN + batch * 32 + l];
        }
        int wl = __ffs(ballot) - 1;                // lowest lane = best rank
        u64 wkey = __shfl_sync(0xffffffffu, key, wl);
        unsigned widx = OUTN - 1 - (unsigned)(wkey & 0xFFFFFFFFu);
        if (l == 0) {
            unsigned m = (unsigned)(wkey >> 32);
            unsigned u = (m & 0x80000000u) ? (m ^ 0x80000000u) : ~m;
            float val = __uint_as_float(u);
            if (t < out_size)       out[t] = (float)widx;
            if (SEQ + t < out_size) out[SEQ + t] = val - lse_c;
            vis[widx >> 5] |= 1u << (widx & 31);
        }
        __syncwarp();

        cur = nxt; lse_c = lse_n;
    }
}

// ---------------- launch ----------------
extern "C" void kernel_launch(void* const* d_in, const int* in_sizes, int n_in,
                              void* d_out, int out_size) {
    const float* X    = (const float*)d_in[0];
    const float* enc  = (const float*)d_in[1];
    const float* Wih  = (const float*)d_in[2];
    const float* Whh  = (const float*)d_in[3];
    const float* bih  = (const float*)d_in[4];
    const float* bhh  = (const float*)d_in[5];
    const float* Wout = (const float*)d_in[6];
    const float* bout = (const float*)d_in[7];
    float* out = (float*)d_out;

    // per-launch resets (graph-capturable async memsets)
    void* doneAddr = nullptr; cudaGetSymbolAddress(&doneAddr, g_done);
    cudaMemsetAsync(doneAddr, 0, (SEQ + 1) * sizeof(unsigned));
    void* hAddr = nullptr; cudaGetSymbolAddress(&hAddr, g_h);
    cudaMemsetAsync(hAddr, 0, H * sizeof(float));   // h_0 = 0

    precompute_gx<<<dim3(16, 32), 256>>>(X, Wih, bih, bhh);
    lstm_recurrence<<<NB, 256>>>(enc, Whh, Wout, bout);
    row_lse<<<SEQ, 256>>>();
    sort_rows<<<SEQ, 256>>>();
    tour_select<<<1, 32>>>(out, out_size);
}